// round 10
// baseline (speedup 1.0000x reference)
#include <cuda_runtime.h>
#include <math.h>
#include <stdint.h>

// CosineAttention: B=64, L=4096, D=1024  — FINAL (R8 form, 148.0us measured).
//   q = l2norm(query); k = l2norm(keys); scores = k @ q; softmax over L + mask.
//
// Kernel 1: one warp per (b,l) key row (MLP-8 LDG.128 stream, ~94% of HBM
//           spec). Accumulates dot(k,q), k.k, q.q in one pass and writes the
//           FINISHED cosine s = dot / (max(||k||,eps)*max(||q||,eps)).
//           NOTE: epilogue must stay minimal — adding mask/exp there (R9) or
//           fusing softmax (R6) or 2 rows/warp (R7) all regressed.
// Kernel 2: one 1024-thread block per batch row. Cosines lie in [-1,1], so
//           softmax needs no max-subtraction (shift-invariant, no overflow):
//           mask -> exp -> single sum-reduction -> scale. Launch-latency
//           floored at ~4.8us regardless of contents.
//
// Inputs bound BY ELEMENT COUNT: query=65536, keys=268435456, mask=262144(int32).

#define B 64
#define L 4096
#define D 1024
#define EPS 1e-12f

#define WARPS_PER_BLOCK 8
#define THREADS1 (WARPS_PER_BLOCK * 32)

__global__ __launch_bounds__(THREADS1)
void cosatt_scores_kernel(const float* __restrict__ query,
                          const float* __restrict__ keys,
                          float* __restrict__ scores)
{
    const int b    = blockIdx.y;
    const int warp = threadIdx.x >> 5;
    const int lane = threadIdx.x & 31;
    const int l    = blockIdx.x * WARPS_PER_BLOCK + warp;

    const float4* __restrict__ krow =
        reinterpret_cast<const float4*>(keys + ((size_t)b * L + l) * D);
    const float4* __restrict__ qrow =
        reinterpret_cast<const float4*>(query + (size_t)b * D);

    float dot = 0.f;
    float kk  = 0.f;
    float qq  = 0.f;

    // 256 float4 per row; 32 lanes x 8 unrolled iters -> MLP ~8 LDG.128.
    #pragma unroll
    for (int i = 0; i < 8; ++i) {
        const int idx = i * 32 + lane;
        float4 kv = __ldcs(&krow[idx]);   // touch-once stream, evict-first
        float4 qv = qrow[idx];            // L1-resident, shared by block
        dot = fmaf(kv.x, qv.x, dot);
        dot = fmaf(kv.y, qv.y, dot);
        dot = fmaf(kv.z, qv.z, dot);
        dot = fmaf(kv.w, qv.w, dot);
        kk  = fmaf(kv.x, kv.x, kk);
        kk  = fmaf(kv.y, kv.y, kk);
        kk  = fmaf(kv.z, kv.z, kk);
        kk  = fmaf(kv.w, kv.w, kk);
        qq  = fmaf(qv.x, qv.x, qq);
        qq  = fmaf(qv.y, qv.y, qq);
        qq  = fmaf(qv.z, qv.z, qq);
        qq  = fmaf(qv.w, qv.w, qq);
    }

    #pragma unroll
    for (int off = 16; off > 0; off >>= 1) {
        dot += __shfl_xor_sync(0xffffffffu, dot, off);
        kk  += __shfl_xor_sync(0xffffffffu, kk,  off);
        qq  += __shfl_xor_sync(0xffffffffu, qq,  off);
    }

    if (lane == 0) {
        float kn = fmaxf(sqrtf(kk), EPS);
        float qn = fmaxf(sqrtf(qq), EPS);
        scores[(size_t)b * L + l] = dot / (kn * qn);
    }
}

#define THREADS2 1024
#define NWARP2 (THREADS2 / 32)

__global__ __launch_bounds__(THREADS2)
void cosatt_softmax_kernel(const int* __restrict__ mask,
                           float* __restrict__ scores /* in/out */)
{
    const int b   = blockIdx.x;
    const int tid = threadIdx.x;

    __shared__ float red[NWARP2];
    __shared__ float s_sum;

    // scores are finished cosines in [-1,1]: softmax needs no max shift.
    const float4* srow = reinterpret_cast<const float4*>(scores + (size_t)b * L);
    const int4*   mrow = reinterpret_cast<const int4*>(mask + (size_t)b * L);

    float4 sv = srow[tid];
    int4   mv = mrow[tid];

    float v0 = mv.x ? __expf(sv.x) : 0.f;
    float v1 = mv.y ? __expf(sv.y) : 0.f;
    float v2 = mv.z ? __expf(sv.z) : 0.f;
    float v3 = mv.w ? __expf(sv.w) : 0.f;

    float sum = (v0 + v1) + (v2 + v3);
    #pragma unroll
    for (int off = 16; off > 0; off >>= 1)
        sum += __shfl_xor_sync(0xffffffffu, sum, off);
    if ((tid & 31) == 0) red[tid >> 5] = sum;
    __syncthreads();
    if (tid < 32) {
        float t = (tid < NWARP2) ? red[tid] : 0.f;
        #pragma unroll
        for (int off = 16; off > 0; off >>= 1)
            t += __shfl_xor_sync(0xffffffffu, t, off);
        if (tid == 0) s_sum = t;
    }
    __syncthreads();
    const float inv_sum = 1.0f / s_sum;

    float4 o;
    o.x = v0 * inv_sum;
    o.y = v1 * inv_sum;
    o.z = v2 * inv_sum;
    o.w = v3 * inv_sum;
    reinterpret_cast<float4*>(scores + (size_t)b * L)[tid] = o;
}

extern "C" void kernel_launch(void* const* d_in, const int* in_sizes, int n_in,
                              void* d_out, int out_size)
{
    const float* query = nullptr;  // B*D   = 65536
    const float* keys  = nullptr;  // B*L*D = 268435456
    const int*   mask  = nullptr;  // B*L   = 262144 (int32)

    for (int i = 0; i < n_in; ++i) {
        if (in_sizes[i] == B * D)      query = (const float*)d_in[i];
        else if (in_sizes[i] == B * L) mask  = (const int*)d_in[i];
        else                           keys  = (const float*)d_in[i];
    }

    float* out = (float*)d_out;  // [B, L] float32

    dim3 grid1(L / WARPS_PER_BLOCK, B);
    cosatt_scores_kernel<<<grid1, THREADS1>>>(query, keys, out);
    cosatt_softmax_kernel<<<B, THREADS2>>>(mask, out);
}

// round 11
// speedup vs baseline: 1.0217x; 1.0217x over previous
#include <cuda_runtime.h>
#include <math.h>
#include <stdint.h>

// CosineAttention: B=64, L=4096, D=1024  — FINAL (R8 form; best 148.0us,
// bench variance established at +/-4-5us on identical source in R10).
//   q = l2norm(query); k = l2norm(keys); scores = k @ q; softmax over L + mask.
//
// Kernel 1: one warp per (b,l) key row (MLP-8 LDG.128 stream, ~94% of HBM
//           spec). Accumulates dot(k,q), k.k, q.q in one pass and writes the
//           FINISHED cosine s = dot / (max(||k||,eps)*max(||q||,eps)).
//           NOTE: epilogue must stay minimal — adding mask/exp there (R9),
//           fusing softmax (R6), or 2 rows/warp (R7) all regressed.
// Kernel 2: one 1024-thread block per batch row. Cosines lie in [-1,1], so
//           softmax needs no max-subtraction (shift-invariant, no overflow):
//           mask -> exp -> single sum-reduction -> scale. Launch-latency
//           floored at ~5us regardless of contents.
//
// Inputs bound BY ELEMENT COUNT: query=65536, keys=268435456, mask=262144(int32).

#define B 64
#define L 4096
#define D 1024
#define EPS 1e-12f

#define WARPS_PER_BLOCK 8
#define THREADS1 (WARPS_PER_BLOCK * 32)

__global__ __launch_bounds__(THREADS1)
void cosatt_scores_kernel(const float* __restrict__ query,
                          const float* __restrict__ keys,
                          float* __restrict__ scores)
{
    const int b    = blockIdx.y;
    const int warp = threadIdx.x >> 5;
    const int lane = threadIdx.x & 31;
    const int l    = blockIdx.x * WARPS_PER_BLOCK + warp;

    const float4* __restrict__ krow =
        reinterpret_cast<const float4*>(keys + ((size_t)b * L + l) * D);
    const float4* __restrict__ qrow =
        reinterpret_cast<const float4*>(query + (size_t)b * D);

    float dot = 0.f;
    float kk  = 0.f;
    float qq  = 0.f;

    // 256 float4 per row; 32 lanes x 8 unrolled iters -> MLP ~8 LDG.128.
    #pragma unroll
    for (int i = 0; i < 8; ++i) {
        const int idx = i * 32 + lane;
        float4 kv = __ldcs(&krow[idx]);   // touch-once stream, evict-first
        float4 qv = qrow[idx];            // L1-resident, shared by block
        dot = fmaf(kv.x, qv.x, dot);
        dot = fmaf(kv.y, qv.y, dot);
        dot = fmaf(kv.z, qv.z, dot);
        dot = fmaf(kv.w, qv.w, dot);
        kk  = fmaf(kv.x, kv.x, kk);
        kk  = fmaf(kv.y, kv.y, kk);
        kk  = fmaf(kv.z, kv.z, kk);
        kk  = fmaf(kv.w, kv.w, kk);
        qq  = fmaf(qv.x, qv.x, qq);
        qq  = fmaf(qv.y, qv.y, qq);
        qq  = fmaf(qv.z, qv.z, qq);
        qq  = fmaf(qv.w, qv.w, qq);
    }

    #pragma unroll
    for (int off = 16; off > 0; off >>= 1) {
        dot += __shfl_xor_sync(0xffffffffu, dot, off);
        kk  += __shfl_xor_sync(0xffffffffu, kk,  off);
        qq  += __shfl_xor_sync(0xffffffffu, qq,  off);
    }

    if (lane == 0) {
        float kn = fmaxf(sqrtf(kk), EPS);
        float qn = fmaxf(sqrtf(qq), EPS);
        scores[(size_t)b * L + l] = dot / (kn * qn);
    }
}

#define THREADS2 1024
#define NWARP2 (THREADS2 / 32)

__global__ __launch_bounds__(THREADS2)
void cosatt_softmax_kernel(const int* __restrict__ mask,
                           float* __restrict__ scores /* in/out */)
{
    const int b   = blockIdx.x;
    const int tid = threadIdx.x;

    __shared__ float red[NWARP2];
    __shared__ float s_sum;

    // scores are finished cosines in [-1,1]: softmax needs no max shift.
    const float4* srow = reinterpret_cast<const float4*>(scores + (size_t)b * L);
    const int4*   mrow = reinterpret_cast<const int4*>(mask + (size_t)b * L);

    float4 sv = srow[tid];
    int4   mv = mrow[tid];

    float v0 = mv.x ? __expf(sv.x) : 0.f;
    float v1 = mv.y ? __expf(sv.y) : 0.f;
    float v2 = mv.z ? __expf(sv.z) : 0.f;
    float v3 = mv.w ? __expf(sv.w) : 0.f;

    float sum = (v0 + v1) + (v2 + v3);
    #pragma unroll
    for (int off = 16; off > 0; off >>= 1)
        sum += __shfl_xor_sync(0xffffffffu, sum, off);
    if ((tid & 31) == 0) red[tid >> 5] = sum;
    __syncthreads();
    if (tid < 32) {
        float t = (tid < NWARP2) ? red[tid] : 0.f;
        #pragma unroll
        for (int off = 16; off > 0; off >>= 1)
            t += __shfl_xor_sync(0xffffffffu, t, off);
        if (tid == 0) s_sum = t;
    }
    __syncthreads();
    const float inv_sum = 1.0f / s_sum;

    float4 o;
    o.x = v0 * inv_sum;
    o.y = v1 * inv_sum;
    o.z = v2 * inv_sum;
    o.w = v3 * inv_sum;
    reinterpret_cast<float4*>(scores + (size_t)b * L)[tid] = o;
}

extern "C" void kernel_launch(void* const* d_in, const int* in_sizes, int n_in,
                              void* d_out, int out_size)
{
    const float* query = nullptr;  // B*D   = 65536
    const float* keys  = nullptr;  // B*L*D = 268435456
    const int*   mask  = nullptr;  // B*L   = 262144 (int32)

    for (int i = 0; i < n_in; ++i) {
        if (in_sizes[i] == B * D)      query = (const float*)d_in[i];
        else if (in_sizes[i] == B * L) mask  = (const int*)d_in[i];
        else                           keys  = (const float*)d_in[i];
    }

    float* out = (float*)d_out;  // [B, L] float32

    dim3 grid1(L / WARPS_PER_BLOCK, B);
    cosatt_scores_kernel<<<grid1, THREADS1>>>(query, keys, out);
    cosatt_softmax_kernel<<<B, THREADS2>>>(mask, out);
}

// round 12
// speedup vs baseline: 1.0324x; 1.0105x over previous
#include <cuda_runtime.h>
#include <math.h>
#include <stdint.h>

// CosineAttention: B=64, L=4096, D=1024  — R8 structure + PDL overlap.
//   q = l2norm(query); k = l2norm(keys); scores = k @ q; softmax over L + mask.
//
// Kernel 1: one warp per (b,l) key row (MLP-8 LDG.128 stream, ~94% of HBM
//           spec). Accumulates dot(k,q), k.k, q.q in one pass and writes the
//           FINISHED cosine s = dot / (max(||k||,eps)*max(||q||,eps)).
//           Epilogue additionally fires the PDL trigger (single instruction,
//           outside the hot loop — R6/R9 showed hot-loop additions regress).
// Kernel 2: PDL secondary (programmaticStreamSerializationAllowed=1): its
//           launch/scheduling overlaps kernel 1's tail; it blocks on
//           cudaGridDependencySynchronize() before reading scores (which also
//           guarantees visibility of kernel 1's stores). Cosines in [-1,1] ->
//           no max pass: mask -> exp -> one sum-reduction -> scale.
//
// Inputs bound BY ELEMENT COUNT: query=65536, keys=268435456, mask=262144(int32).

#define B 64
#define L 4096
#define D 1024
#define EPS 1e-12f

#define WARPS_PER_BLOCK 8
#define THREADS1 (WARPS_PER_BLOCK * 32)

__global__ __launch_bounds__(THREADS1)
void cosatt_scores_kernel(const float* __restrict__ query,
                          const float* __restrict__ keys,
                          float* __restrict__ scores)
{
    const int b    = blockIdx.y;
    const int warp = threadIdx.x >> 5;
    const int lane = threadIdx.x & 31;
    const int l    = blockIdx.x * WARPS_PER_BLOCK + warp;

    const float4* __restrict__ krow =
        reinterpret_cast<const float4*>(keys + ((size_t)b * L + l) * D);
    const float4* __restrict__ qrow =
        reinterpret_cast<const float4*>(query + (size_t)b * D);

    float dot = 0.f;
    float kk  = 0.f;
    float qq  = 0.f;

    // 256 float4 per row; 32 lanes x 8 unrolled iters -> MLP ~8 LDG.128.
    #pragma unroll
    for (int i = 0; i < 8; ++i) {
        const int idx = i * 32 + lane;
        float4 kv = __ldcs(&krow[idx]);   // touch-once stream, evict-first
        float4 qv = qrow[idx];            // L1-resident, shared by block
        dot = fmaf(kv.x, qv.x, dot);
        dot = fmaf(kv.y, qv.y, dot);
        dot = fmaf(kv.z, qv.z, dot);
        dot = fmaf(kv.w, qv.w, dot);
        kk  = fmaf(kv.x, kv.x, kk);
        kk  = fmaf(kv.y, kv.y, kk);
        kk  = fmaf(kv.z, kv.z, kk);
        kk  = fmaf(kv.w, kv.w, kk);
        qq  = fmaf(qv.x, qv.x, qq);
        qq  = fmaf(qv.y, qv.y, qq);
        qq  = fmaf(qv.z, qv.z, qq);
        qq  = fmaf(qv.w, qv.w, qq);
    }

    #pragma unroll
    for (int off = 16; off > 0; off >>= 1) {
        dot += __shfl_xor_sync(0xffffffffu, dot, off);
        kk  += __shfl_xor_sync(0xffffffffu, kk,  off);
        qq  += __shfl_xor_sync(0xffffffffu, qq,  off);
    }

    if (lane == 0) {
        float kn = fmaxf(sqrtf(kk), EPS);
        float qn = fmaxf(sqrtf(qq), EPS);
        scores[(size_t)b * L + l] = dot / (kn * qn);
    }

    // PDL: allow the softmax kernel's launch to begin overlapping our tail.
    cudaTriggerProgrammaticLaunchCompletion();
}

#define THREADS2 1024
#define NWARP2 (THREADS2 / 32)

__global__ __launch_bounds__(THREADS2)
void cosatt_softmax_kernel(const int* __restrict__ mask,
                           float* __restrict__ scores /* in/out */)
{
    const int b   = blockIdx.x;
    const int tid = threadIdx.x;

    __shared__ float red[NWARP2];
    __shared__ float s_sum;

    // Block until the primary grid's stores are visible.
    cudaGridDependencySynchronize();

    // scores are finished cosines in [-1,1]: softmax needs no max shift.
    const float4* srow = reinterpret_cast<const float4*>(scores + (size_t)b * L);
    const int4*   mrow = reinterpret_cast<const int4*>(mask + (size_t)b * L);

    float4 sv = srow[tid];
    int4   mv = mrow[tid];

    float v0 = mv.x ? __expf(sv.x) : 0.f;
    float v1 = mv.y ? __expf(sv.y) : 0.f;
    float v2 = mv.z ? __expf(sv.z) : 0.f;
    float v3 = mv.w ? __expf(sv.w) : 0.f;

    float sum = (v0 + v1) + (v2 + v3);
    #pragma unroll
    for (int off = 16; off > 0; off >>= 1)
        sum += __shfl_xor_sync(0xffffffffu, sum, off);
    if ((tid & 31) == 0) red[tid >> 5] = sum;
    __syncthreads();
    if (tid < 32) {
        float t = (tid < NWARP2) ? red[tid] : 0.f;
        #pragma unroll
        for (int off = 16; off > 0; off >>= 1)
            t += __shfl_xor_sync(0xffffffffu, t, off);
        if (tid == 0) s_sum = t;
    }
    __syncthreads();
    const float inv_sum = 1.0f / s_sum;

    float4 o;
    o.x = v0 * inv_sum;
    o.y = v1 * inv_sum;
    o.z = v2 * inv_sum;
    o.w = v3 * inv_sum;
    reinterpret_cast<float4*>(scores + (size_t)b * L)[tid] = o;
}

extern "C" void kernel_launch(void* const* d_in, const int* in_sizes, int n_in,
                              void* d_out, int out_size)
{
    const float* query = nullptr;  // B*D   = 65536
    const float* keys  = nullptr;  // B*L*D = 268435456
    const int*   mask  = nullptr;  // B*L   = 262144 (int32)

    for (int i = 0; i < n_in; ++i) {
        if (in_sizes[i] == B * D)      query = (const float*)d_in[i];
        else if (in_sizes[i] == B * L) mask  = (const int*)d_in[i];
        else                           keys  = (const float*)d_in[i];
    }

    float* out = (float*)d_out;  // [B, L] float32

    dim3 grid1(L / WARPS_PER_BLOCK, B);
    cosatt_scores_kernel<<<grid1, THREADS1>>>(query, keys, out);

    // Secondary launch with programmatic dependent launch (PDL): its setup
    // overlaps the primary's tail; correctness is enforced by the
    // cudaGridDependencySynchronize() inside the kernel.
    cudaLaunchConfig_t cfg = {};
    cfg.gridDim  = dim3(B);
    cfg.blockDim = dim3(THREADS2);
    cudaLaunchAttribute attrs[1];
    attrs[0].id = cudaLaunchAttributeProgrammaticStreamSerialization;
    attrs[0].val.programmaticStreamSerializationAllowed = 1;
    cfg.attrs = attrs;
    cfg.numAttrs = 1;
    cudaLaunchKernelEx(&cfg, cosatt_softmax_kernel, mask, out);
}

// round 13
// speedup vs baseline: 1.0364x; 1.0039x over previous
#include <cuda_runtime.h>
#include <math.h>
#include <stdint.h>

// CosineAttention: B=64, L=4096, D=1024  — FINAL CANDIDATE: R8 structure + PDL.
//   q = l2norm(query); k = l2norm(keys); scores = k @ q; softmax over L + mask.
//
// Kernel 1: one warp per (b,l) key row (MLP-8 LDG.128 stream, ~93% of HBM
//           spec — converged; R6 fusion, R7 multi-row, R9 epilogue-work all
//           measured and regressed). Accumulates dot(k,q), k.k, q.q in one
//           pass, writes finished cosine s = dot/(max(||k||,eps)*max(||q||,eps)).
//           Epilogue fires the PDL trigger (single instruction, outside the
//           hot loop; R12 confirmed no perturbation).
// Kernel 2: PDL secondary — launch/scheduling overlaps kernel 1's drain;
//           cudaGridDependencySynchronize() guarantees store visibility.
//           Cosines in [-1,1] -> no max pass: mask -> exp -> sum -> scale.
//
// Inputs bound BY ELEMENT COUNT: query=65536, keys=268435456, mask=262144(int32).

#define B 64
#define L 4096
#define D 1024
#define EPS 1e-12f

#define WARPS_PER_BLOCK 8
#define THREADS1 (WARPS_PER_BLOCK * 32)

__global__ __launch_bounds__(THREADS1)
void cosatt_scores_kernel(const float* __restrict__ query,
                          const float* __restrict__ keys,
                          float* __restrict__ scores)
{
    const int b    = blockIdx.y;
    const int warp = threadIdx.x >> 5;
    const int lane = threadIdx.x & 31;
    const int l    = blockIdx.x * WARPS_PER_BLOCK + warp;

    const float4* __restrict__ krow =
        reinterpret_cast<const float4*>(keys + ((size_t)b * L + l) * D);
    const float4* __restrict__ qrow =
        reinterpret_cast<const float4*>(query + (size_t)b * D);

    float dot = 0.f;
    float kk  = 0.f;
    float qq  = 0.f;

    // 256 float4 per row; 32 lanes x 8 unrolled iters -> MLP ~8 LDG.128.
    #pragma unroll
    for (int i = 0; i < 8; ++i) {
        const int idx = i * 32 + lane;
        float4 kv = __ldcs(&krow[idx]);   // touch-once stream, evict-first
        float4 qv = qrow[idx];            // L1-resident, shared by block
        dot = fmaf(kv.x, qv.x, dot);
        dot = fmaf(kv.y, qv.y, dot);
        dot = fmaf(kv.z, qv.z, dot);
        dot = fmaf(kv.w, qv.w, dot);
        kk  = fmaf(kv.x, kv.x, kk);
        kk  = fmaf(kv.y, kv.y, kk);
        kk  = fmaf(kv.z, kv.z, kk);
        kk  = fmaf(kv.w, kv.w, kk);
        qq  = fmaf(qv.x, qv.x, qq);
        qq  = fmaf(qv.y, qv.y, qq);
        qq  = fmaf(qv.z, qv.z, qq);
        qq  = fmaf(qv.w, qv.w, qq);
    }

    #pragma unroll
    for (int off = 16; off > 0; off >>= 1) {
        dot += __shfl_xor_sync(0xffffffffu, dot, off);
        kk  += __shfl_xor_sync(0xffffffffu, kk,  off);
        qq  += __shfl_xor_sync(0xffffffffu, qq,  off);
    }

    if (lane == 0) {
        float kn = fmaxf(sqrtf(kk), EPS);
        float qn = fmaxf(sqrtf(qq), EPS);
        scores[(size_t)b * L + l] = dot / (kn * qn);
    }

    // PDL: allow the softmax kernel's launch to begin overlapping our tail.
    cudaTriggerProgrammaticLaunchCompletion();
}

#define THREADS2 1024
#define NWARP2 (THREADS2 / 32)

__global__ __launch_bounds__(THREADS2)
void cosatt_softmax_kernel(const int* __restrict__ mask,
                           float* __restrict__ scores /* in/out */)
{
    const int b   = blockIdx.x;
    const int tid = threadIdx.x;

    __shared__ float red[NWARP2];
    __shared__ float s_sum;

    // Block until the primary grid's stores are visible.
    cudaGridDependencySynchronize();

    // scores are finished cosines in [-1,1]: softmax needs no max shift.
    const float4* srow = reinterpret_cast<const float4*>(scores + (size_t)b * L);
    const int4*   mrow = reinterpret_cast<const int4*>(mask + (size_t)b * L);

    float4 sv = srow[tid];
    int4   mv = mrow[tid];

    float v0 = mv.x ? __expf(sv.x) : 0.f;
    float v1 = mv.y ? __expf(sv.y) : 0.f;
    float v2 = mv.z ? __expf(sv.z) : 0.f;
    float v3 = mv.w ? __expf(sv.w) : 0.f;

    float sum = (v0 + v1) + (v2 + v3);
    #pragma unroll
    for (int off = 16; off > 0; off >>= 1)
        sum += __shfl_xor_sync(0xffffffffu, sum, off);
    if ((tid & 31) == 0) red[tid >> 5] = sum;
    __syncthreads();
    if (tid < 32) {
        float t = (tid < NWARP2) ? red[tid] : 0.f;
        #pragma unroll
        for (int off = 16; off > 0; off >>= 1)
            t += __shfl_xor_sync(0xffffffffu, t, off);
        if (tid == 0) s_sum = t;
    }
    __syncthreads();
    const float inv_sum = 1.0f / s_sum;

    float4 o;
    o.x = v0 * inv_sum;
    o.y = v1 * inv_sum;
    o.z = v2 * inv_sum;
    o.w = v3 * inv_sum;
    reinterpret_cast<float4*>(scores + (size_t)b * L)[tid] = o;
}

extern "C" void kernel_launch(void* const* d_in, const int* in_sizes, int n_in,
                              void* d_out, int out_size)
{
    const float* query = nullptr;  // B*D   = 65536
    const float* keys  = nullptr;  // B*L*D = 268435456
    const int*   mask  = nullptr;  // B*L   = 262144 (int32)

    for (int i = 0; i < n_in; ++i) {
        if (in_sizes[i] == B * D)      query = (const float*)d_in[i];
        else if (in_sizes[i] == B * L) mask  = (const int*)d_in[i];
        else                           keys  = (const float*)d_in[i];
    }

    float* out = (float*)d_out;  // [B, L] float32

    dim3 grid1(L / WARPS_PER_BLOCK, B);
    cosatt_scores_kernel<<<grid1, THREADS1>>>(query, keys, out);

    // Secondary launch with programmatic dependent launch (PDL): its setup
    // overlaps the primary's tail; correctness is enforced by the
    // cudaGridDependencySynchronize() inside the kernel.
    cudaLaunchConfig_t cfg = {};
    cfg.gridDim  = dim3(B);
    cfg.blockDim = dim3(THREADS2);
    cudaLaunchAttribute attrs[1];
    attrs[0].id = cudaLaunchAttributeProgrammaticStreamSerialization;
    attrs[0].val.programmaticStreamSerializationAllowed = 1;
    cfg.attrs = attrs;
    cfg.numAttrs = 1;
    cudaLaunchKernelEx(&cfg, cosatt_softmax_kernel, mask, out);
}